// round 1
// baseline (speedup 1.0000x reference)
#include <cuda_runtime.h>

#define BB 8
#define NN 4096
#define EE 8190
#define VV 256
#define HH 128
#define NW 128   // bitmask words per adjacency row (4096/32)

// -------- scratch (device globals; zero-initialized at load, re-cleared per call) --------
__device__ unsigned int g_mask[BB * NN * NW];   // 16.7 MB dedup bitmask
__device__ float        g_S[BB * NN * HH];      // 16.7 MB per-node neighbor sum (of emb1)
__device__ float        g_insum[BB * NN];       // incoming dis sum per node (colsum helper)
__device__ int          g_rowcnt[BB * NN];      // unique out-degree per node
__device__ float        g_dis[BB * NN];         // deg^-1/2
__device__ float        g_emb1[VV * HH];        // emb @ w1^T  (256 x 128)
__device__ float        g_pooled[BB * HH];      // sum_j c_j * h_j
__device__ unsigned int g_ulist[BB * EE];       // packed unique edges (b<<24 | i<<12 | j)
__device__ int          g_ne;                   // number of unique edges

// -------- K0: clear scratch --------
__global__ void k_clear() {
    size_t idx = (size_t)blockIdx.x * blockDim.x + threadIdx.x;
    size_t stride = (size_t)gridDim.x * blockDim.x;
    float4 z4 = make_float4(0.f, 0.f, 0.f, 0.f);
    uint4  u4 = make_uint4(0u, 0u, 0u, 0u);
    float4* s = reinterpret_cast<float4*>(g_S);
    uint4*  m = reinterpret_cast<uint4*>(g_mask);
    const size_t n4 = (size_t)BB * NN * HH / 4;   // 1,048,576
    for (size_t i = idx; i < n4; i += stride) { s[i] = z4; m[i] = u4; }
    for (size_t i = idx; i < (size_t)BB * NN; i += stride) { g_insum[i] = 0.f; g_rowcnt[i] = 0; }
    for (size_t i = idx; i < (size_t)BB * HH; i += stride) g_pooled[i] = 0.f;
    if (idx == 0) g_ne = 0;
}

// -------- K1: edge scatter + dedup (set semantics) --------
__global__ void k_scatter(const int* __restrict__ edges) {
    int t = blockIdx.x * blockDim.x + threadIdx.x;
    if (t >= BB * EE) return;
    int b = t / EE;
    int i = edges[2 * t];
    int j = edges[2 * t + 1];
    unsigned int bit = 1u << (j & 31);
    unsigned int old = atomicOr(&g_mask[((size_t)b * NN + i) * NW + (j >> 5)], bit);
    if (!(old & bit)) {
        int slot = atomicAdd(&g_ne, 1);
        g_ulist[slot] = ((unsigned)b << 24) | ((unsigned)i << 12) | (unsigned)j;
        atomicAdd(&g_rowcnt[b * NN + i], 1);
    }
}

// -------- K2: dis = rsqrt(deg) ; emb1 = emb @ w1^T --------
// grid = 160 blocks x 256 threads: blocks [0,128) do dis, [128,160) do emb1
__global__ void k_dis_emb1(const float* __restrict__ emb, const float* __restrict__ w1) {
    int t = blockIdx.x * blockDim.x + threadIdx.x;
    if (blockIdx.x < 128) {
        // deg = unique-out-edges + 1 (identity); deg >= 1 so no clamp needed
        g_dis[t] = rsqrtf(1.0f + (float)g_rowcnt[t]);
    } else {
        int local = t - 128 * 256;              // [0, 8192)
        #pragma unroll
        for (int r = 0; r < 4; r++) {
            int o = local + r * 8192;           // [0, 32768)
            int v = o >> 7, c = o & 127;
            const float* er = emb + v * HH;
            const float* wr = w1 + c * HH;
            float acc = 0.f;
            #pragma unroll 8
            for (int k = 0; k < HH; k++) acc = fmaf(er[k], wr[k], acc);
            g_emb1[o] = acc;
        }
    }
}

// -------- K3: per unique edge: S[b,i,:] += dis_j * emb1[type_j]; insum[j] += dis_i --------
__global__ void k_edge(const int* __restrict__ type_ids) {
    int t = blockIdx.x * blockDim.x + threadIdx.x;
    int e = t >> 7;
    int d = t & 127;
    if (e >= g_ne) return;
    unsigned u = g_ulist[e];
    int b = u >> 24;
    int i = (u >> 12) & 4095;
    int j = u & 4095;
    float dj = g_dis[b * NN + j];
    int   tj = type_ids[b * NN + j];
    atomicAdd(&g_S[((size_t)b * NN + i) * HH + d], dj * g_emb1[tj * HH + d]);
    if (d == 0) atomicAdd(&g_insum[b * NN + j], g_dis[b * NN + i]);
}

// -------- K4: per node: h = relu(dis_i*(dis_i*emb1[t_i] + S_i) + b1); pooled += c_i * h ----
// grid = (128, 8), block = 128 (thread = H dim); 32 nodes per block
__global__ void k_node(const int* __restrict__ type_ids, const float* __restrict__ b1) {
    int b = blockIdx.y;
    int t = threadIdx.x;
    float bias = b1[t];
    float acc = 0.f;
    int start = blockIdx.x * (NN / 128);   // 32 nodes each
    for (int i = start; i < start + (NN / 128); i++) {
        int ni = b * NN + i;
        float di = g_dis[ni];
        int   ti = type_ids[ni];
        float s  = g_S[(size_t)ni * HH + t];
        float e1 = g_emb1[ti * HH + t];
        float hv = fmaf(di, fmaf(di, e1, s), bias);
        hv = fmaxf(hv, 0.f);
        float c = di * (di + g_insum[ni]);
        acc = fmaf(c, hv, acc);
    }
    atomicAdd(&g_pooled[b * HH + t], acc);
}

// -------- K5: zbar = (pooled/N) @ w2^T + b2, L2-normalize, write out --------
__global__ void k_final(const float* __restrict__ w2, const float* __restrict__ b2,
                        float* __restrict__ out) {
    __shared__ float xs[HH];
    __shared__ float red[4];
    int t = threadIdx.x;
    for (int b = 0; b < BB; b++) {
        xs[t] = g_pooled[b * HH + t] * (1.0f / NN);
        __syncthreads();
        float z = b2[t];
        const float* wr = w2 + t * HH;
        #pragma unroll 8
        for (int k = 0; k < HH; k++) z = fmaf(wr[k], xs[k], z);
        float sq = z * z;
        #pragma unroll
        for (int o = 16; o > 0; o >>= 1) sq += __shfl_xor_sync(0xffffffffu, sq, o);
        if ((t & 31) == 0) red[t >> 5] = sq;
        __syncthreads();
        float nrm = sqrtf(red[0] + red[1] + red[2] + red[3]);
        nrm = fmaxf(nrm, 1e-12f);
        out[b * HH + t] = z / nrm;
        __syncthreads();
    }
}

extern "C" void kernel_launch(void* const* d_in, const int* in_sizes, int n_in,
                              void* d_out, int out_size) {
    const int*   type_ids = (const int*)d_in[0];
    const int*   edges    = (const int*)d_in[1];
    const float* emb      = (const float*)d_in[2];
    const float* w1       = (const float*)d_in[3];
    const float* b1       = (const float*)d_in[4];
    const float* w2       = (const float*)d_in[5];
    const float* b2       = (const float*)d_in[6];
    float* out = (float*)d_out;

    k_clear<<<2048, 256>>>();
    k_scatter<<<(BB * EE + 255) / 256, 256>>>(edges);
    k_dis_emb1<<<160, 256>>>(emb, w1);
    k_edge<<<(BB * EE * HH) / 256, 256>>>(type_ids);   // 32760 blocks exactly
    dim3 g4(128, BB);
    k_node<<<g4, 128>>>(type_ids, b1);
    k_final<<<1, 128>>>(w2, b2, out);
}

// round 2
// speedup vs baseline: 1.0481x; 1.0481x over previous
#include <cuda_runtime.h>

#define BB 8
#define NN 4096
#define EE 8190
#define VV 256
#define HH 128
#define TS 131072          // hash table slots (2^17, load factor 0.5)
#define TSM (TS - 1)
#define CAP 32             // adjacency capacity per node (Poisson(2): P(>32) ~ e^-60)

// -------- scratch (device globals) --------
__device__ unsigned int g_tab[TS];           // 512KB dedup hash table (key+1, 0=empty)
__device__ int          g_rowcnt[BB * NN];   // unique out-degree per node
__device__ int          g_wcur[BB * NN];     // adjacency write cursor
__device__ float        g_insum[BB * NN];    // incoming dis sum per node
__device__ float        g_dis[BB * NN];      // deg^-1/2
__device__ float        g_emb1[VV * HH];     // emb @ w1^T  (256 x 128, L2-resident)
__device__ float        g_pooled[BB * HH];   // sum_j c_j * h_j
__device__ float2       g_adj[(size_t)BB * NN * CAP]; // per-neighbor (dis_j, type_j-as-bits)

// -------- K0: clear small scratch (~1MB total) --------
__global__ void k_clear() {
    int t = blockIdx.x * blockDim.x + threadIdx.x;   // 32768 threads
    g_rowcnt[t] = 0;
    g_wcur[t] = 0;
    g_insum[t] = 0.f;
    reinterpret_cast<uint4*>(g_tab)[t] = make_uint4(0u, 0u, 0u, 0u); // 32768*16B = TS*4B
    if (t < BB * HH) g_pooled[t] = 0.f;
}

// -------- K1: edge dedup via hash table (set semantics) --------
__global__ void k_scatter(const int* __restrict__ edges) {
    int t = blockIdx.x * blockDim.x + threadIdx.x;
    if (t >= BB * EE) return;
    int b = t / EE;
    int i = edges[2 * t];
    int j = edges[2 * t + 1];
    unsigned key1 = ((((unsigned)b << 24) | ((unsigned)i << 12) | (unsigned)j)) + 1u;
    unsigned s = (key1 * 0x9E3779B1u) >> 15;   // top 17 bits
    s &= TSM;
    while (true) {
        unsigned prev = atomicCAS(&g_tab[s], 0u, key1);
        if (prev == 0u) {                       // first inserter wins
            atomicAdd(&g_rowcnt[b * NN + i], 1);
            break;
        }
        if (prev == key1) break;                // duplicate edge: drop
        s = (s + 1) & TSM;                      // linear probe
    }
}

// -------- K2: dis = rsqrt(deg) ; emb1 = emb @ w1^T --------
// grid = 160 blocks x 256 threads: blocks [0,128) do dis, [128,160) do emb1
__global__ void k_dis_emb1(const float* __restrict__ emb, const float* __restrict__ w1) {
    int t = blockIdx.x * blockDim.x + threadIdx.x;
    if (blockIdx.x < 128) {
        // deg = unique-out-edges + 1 (identity); deg >= 1 so no clamp needed
        g_dis[t] = rsqrtf(1.0f + (float)g_rowcnt[t]);
    } else {
        int local = t - 128 * 256;              // [0, 8192)
        #pragma unroll
        for (int r = 0; r < 4; r++) {
            int o = local + r * 8192;           // [0, 32768)
            int v = o >> 7, c = o & 127;
            const float* er = emb + v * HH;
            const float* wr = w1 + c * HH;
            float acc = 0.f;
            #pragma unroll 8
            for (int k = 0; k < HH; k++) acc = fmaf(er[k], wr[k], acc);
            g_emb1[o] = acc;
        }
    }
}

// -------- K3: iterate hash table -> build adjacency with prefetched (dis_j, type_j);
//              accumulate insum[j] += dis_i --------
__global__ void k_fill(const int* __restrict__ type_ids) {
    int s = blockIdx.x * blockDim.x + threadIdx.x;   // TS threads
    unsigned k1 = g_tab[s];
    if (!k1) return;
    unsigned key = k1 - 1u;
    int b = key >> 24;
    int i = (key >> 12) & 4095;
    int j = key & 4095;
    int ni = b * NN + i;
    int nj = b * NN + j;
    int c = atomicAdd(&g_wcur[ni], 1);
    float dj = g_dis[nj];
    int   tj = type_ids[nj];
    g_adj[(size_t)ni * CAP + c] = make_float2(dj, __int_as_float(tj));
    atomicAdd(&g_insum[nj], g_dis[ni]);
}

// -------- K4: per node: h = relu(di*(di*e1 + S) + b1); pooled += c_i * h --------
// grid = (512, 8), block = 128 (thread = H dim); 8 nodes per block
__global__ void k_node(const int* __restrict__ type_ids, const float* __restrict__ b1) {
    int b = blockIdx.y;
    int t = threadIdx.x;
    float bias = b1[t];
    float acc = 0.f;
    int start = blockIdx.x * 8;
    #pragma unroll
    for (int i = start; i < start + 8; i++) {
        int ni = b * NN + i;
        float di  = g_dis[ni];
        int   deg = g_rowcnt[ni];
        int   ti  = type_ids[ni];
        float s = di * g_emb1[ti * HH + t];       // identity (self) term
        for (int d = 0; d < deg; d++) {
            float2 en = g_adj[(size_t)ni * CAP + d];
            s = fmaf(en.x, g_emb1[__float_as_int(en.y) * HH + t], s);
        }
        float hv = fmaf(di, s, bias);
        hv = fmaxf(hv, 0.f);
        float c = di * (di + g_insum[ni]);
        acc = fmaf(c, hv, acc);
    }
    atomicAdd(&g_pooled[b * HH + t], acc);
}

// -------- K5: zbar = (pooled/N) @ w2^T + b2, L2-normalize, write out --------
__global__ void k_final(const float* __restrict__ w2, const float* __restrict__ b2,
                        float* __restrict__ out) {
    __shared__ float xs[HH];
    __shared__ float red[4];
    int t = threadIdx.x;
    for (int b = 0; b < BB; b++) {
        xs[t] = g_pooled[b * HH + t] * (1.0f / NN);
        __syncthreads();
        float z = b2[t];
        const float* wr = w2 + t * HH;
        #pragma unroll 8
        for (int k = 0; k < HH; k++) z = fmaf(wr[k], xs[k], z);
        float sq = z * z;
        #pragma unroll
        for (int o = 16; o > 0; o >>= 1) sq += __shfl_xor_sync(0xffffffffu, sq, o);
        if ((t & 31) == 0) red[t >> 5] = sq;
        __syncthreads();
        float nrm = sqrtf(red[0] + red[1] + red[2] + red[3]);
        nrm = fmaxf(nrm, 1e-12f);
        out[b * HH + t] = z / nrm;
        __syncthreads();
    }
}

extern "C" void kernel_launch(void* const* d_in, const int* in_sizes, int n_in,
                              void* d_out, int out_size) {
    const int*   type_ids = (const int*)d_in[0];
    const int*   edges    = (const int*)d_in[1];
    const float* emb      = (const float*)d_in[2];
    const float* w1       = (const float*)d_in[3];
    const float* b1       = (const float*)d_in[4];
    const float* w2       = (const float*)d_in[5];
    const float* b2       = (const float*)d_in[6];
    float* out = (float*)d_out;

    k_clear<<<128, 256>>>();
    k_scatter<<<(BB * EE + 255) / 256, 256>>>(edges);
    k_dis_emb1<<<160, 256>>>(emb, w1);
    k_fill<<<TS / 256, 256>>>(type_ids);
    dim3 g4(512, BB);
    k_node<<<g4, 128>>>(type_ids, b1);
    k_final<<<1, 128>>>(w2, b2, out);
}

// round 3
// speedup vs baseline: 1.5125x; 1.4430x over previous
#include <cuda_runtime.h>

#define BB 8
#define NN 4096
#define EE 8190
#define VV 256
#define HH 128
#define TS 131072          // hash table slots (2^17, load factor 0.5)
#define TSM (TS - 1)
#define CAP 32             // adjacency capacity per node
#define GG 132             // persistent blocks (<= 148 SMs -> single wave, safe barrier)
#define TT 256             // threads per block

// -------- scratch (device globals) --------
__device__ unsigned int g_tab[TS];           // 512KB dedup hash table (key+1, 0=empty)
__device__ int          g_rowcnt[BB * NN];   // unique out-degree per node
__device__ int          g_wcur[BB * NN];     // adjacency write cursor
__device__ float        g_insum[BB * NN];    // incoming dis sum per node
__device__ float        g_dis[BB * NN];      // deg^-1/2
__device__ float        g_emb1[VV * HH];     // emb @ w1^T
__device__ float        g_pooled[BB * HH];   // sum_j c_j * h_j
__device__ float        g_z[BB * HH];        // pre-normalization output
__device__ float2       g_adj[(size_t)BB * NN * CAP]; // (dis_j, type_j bits)
__device__ unsigned int g_bar_cnt;           // grid barrier arrive counter
__device__ unsigned int g_bar_gen;           // grid barrier generation

__device__ __forceinline__ void gridbar() {
    __syncthreads();
    if (threadIdx.x == 0) {
        __threadfence();   // release: publishes this block's phase writes (cumulative)
        unsigned gen = *((volatile unsigned*)&g_bar_gen);
        if (atomicAdd(&g_bar_cnt, 1u) == gridDim.x - 1) {
            *((volatile unsigned*)&g_bar_cnt) = 0u;
            __threadfence();
            *((volatile unsigned*)&g_bar_gen) = gen + 1u;
        } else {
            while (*((volatile unsigned*)&g_bar_gen) == gen) { }
            __threadfence();   // acquire
        }
    }
    __syncthreads();
}

__global__ void __launch_bounds__(TT, 1)
gnn_all(const int* __restrict__ type_ids, const int* __restrict__ edges,
        const float* __restrict__ emb, const float* __restrict__ w1,
        const float* __restrict__ b1, const float* __restrict__ w2,
        const float* __restrict__ b2, float* __restrict__ out) {
    const int tid  = threadIdx.x;
    const int gtid = blockIdx.x * TT + tid;
    const int gsz  = GG * TT;                 // 33792
    const int lane = tid & 31;
    const int gw   = gtid >> 5;               // global warp id
    const int nw   = gsz >> 5;                // 1056 warps

    // ---- P0: clear scratch (~0.8 MB) ----
    for (int i = gtid; i < TS / 4; i += gsz)
        reinterpret_cast<uint4*>(g_tab)[i] = make_uint4(0u, 0u, 0u, 0u);
    for (int i = gtid; i < BB * NN; i += gsz) {
        g_rowcnt[i] = 0; g_wcur[i] = 0; g_insum[i] = 0.f;
    }
    for (int i = gtid; i < BB * HH; i += gsz) g_pooled[i] = 0.f;
    gridbar();

    // ---- P1: edge dedup (set semantics) + emb1 = emb @ w1^T (warp dots, coalesced) ----
    for (int t = gtid; t < BB * EE; t += gsz) {
        int b = t / EE;
        int i = edges[2 * t];
        int j = edges[2 * t + 1];
        unsigned key1 = (((unsigned)b << 24) | ((unsigned)i << 12) | (unsigned)j) + 1u;
        unsigned s = ((key1 * 0x9E3779B1u) >> 15) & TSM;
        while (true) {
            unsigned prev = atomicCAS(&g_tab[s], 0u, key1);
            if (prev == 0u) { atomicAdd(&g_rowcnt[b * NN + i], 1); break; }
            if (prev == key1) break;
            s = (s + 1) & TSM;
        }
    }
    for (int o = gw; o < VV * HH; o += nw) {
        int v = o >> 7, c = o & 127;
        const float* er = emb + v * HH;
        const float* wr = w1 + c * HH;
        float p = 0.f;
        #pragma unroll
        for (int q = 0; q < 4; q++) { int k = lane + q * 32; p = fmaf(er[k], wr[k], p); }
        #pragma unroll
        for (int off = 16; off; off >>= 1) p += __shfl_xor_sync(0xffffffffu, p, off);
        if (lane == 0) g_emb1[o] = p;
    }
    gridbar();

    // ---- P2: dis = rsqrt(deg); deg = unique edges + 1 (identity) ----
    for (int i = gtid; i < BB * NN; i += gsz)
        g_dis[i] = rsqrtf(1.0f + (float)g_rowcnt[i]);
    gridbar();

    // ---- P3: sweep hash table -> adjacency (prefetched dis_j, type_j) + insum ----
    for (int s = gtid; s < TS; s += gsz) {
        unsigned k1 = g_tab[s];
        if (!k1) continue;
        unsigned key = k1 - 1u;
        int b = key >> 24;
        int i = (key >> 12) & 4095;
        int j = key & 4095;
        int ni = b * NN + i;
        int nj = b * NN + j;
        int c = atomicAdd(&g_wcur[ni], 1);
        if (c < CAP)
            g_adj[(size_t)ni * CAP + c] = make_float2(g_dis[nj], __int_as_float(type_ids[nj]));
        atomicAdd(&g_insum[nj], g_dis[ni]);
    }
    gridbar();

    // ---- P4: per node h = relu(di*(di*e1 + S) + b1); pooled += c_i * h ----
    // 264 groups of 128 threads; 256 chunks of 128 nodes (one batch each)
    {
        const int grp = (blockIdx.x << 1) | (tid >> 7);
        const int t7  = tid & 127;
        const float bias = b1[t7];
        for (int chunk = grp; chunk < 256; chunk += (GG << 1)) {
            int b = chunk >> 5;
            int base = b * NN + (chunk & 31) * 128;
            float acc = 0.f;
            for (int n0 = 0; n0 < 128; n0 += 4) {
                float di[4], ins[4]; int deg[4], ti[4];
                #pragma unroll
                for (int u = 0; u < 4; u++) {
                    int ni = base + n0 + u;
                    di[u]  = g_dis[ni];
                    deg[u] = min(g_rowcnt[ni], CAP);
                    ti[u]  = type_ids[ni];
                    ins[u] = g_insum[ni];
                }
                #pragma unroll
                for (int u = 0; u < 4; u++) {
                    int ni = base + n0 + u;
                    float s = di[u] * g_emb1[ti[u] * HH + t7];
                    const float2* ap = g_adj + (size_t)ni * CAP;
                    for (int d = 0; d < deg[u]; d++) {
                        float2 en = ap[d];
                        s = fmaf(en.x, g_emb1[__float_as_int(en.y) * HH + t7], s);
                    }
                    float hv = fmaxf(fmaf(di[u], s, bias), 0.f);
                    acc = fmaf(di[u] * (di[u] + ins[u]), hv, acc);
                }
            }
            atomicAdd(&g_pooled[b * HH + t7], acc);
        }
    }
    gridbar();

    // ---- P5: z[b,t] = dot(w2[t,:], pooled[b,:])/N + b2[t]  (warp dots, coalesced) ----
    for (int o = gw; o < BB * HH; o += nw) {
        int b = o >> 7, t = o & 127;
        const float* wr = w2 + t * HH;
        const float* xp = g_pooled + b * HH;
        float p = 0.f;
        #pragma unroll
        for (int q = 0; q < 4; q++) { int k = lane + q * 32; p = fmaf(wr[k], xp[k], p); }
        #pragma unroll
        for (int off = 16; off; off >>= 1) p += __shfl_xor_sync(0xffffffffu, p, off);
        if (lane == 0) g_z[o] = fmaf(p, 1.0f / NN, b2[t]);
    }
    gridbar();

    // ---- P6: L2-normalize per batch, write out (block 0 only) ----
    if (blockIdx.x == 0) {
        __shared__ float red[4];
        for (int b = 0; b < BB; b++) {
            float z = (tid < 128) ? g_z[b * HH + tid] : 0.f;
            float sq = z * z;
            #pragma unroll
            for (int off = 16; off; off >>= 1) sq += __shfl_xor_sync(0xffffffffu, sq, off);
            if (tid < 128 && (tid & 31) == 0) red[tid >> 5] = sq;
            __syncthreads();
            if (tid < 128) {
                float nrm = fmaxf(sqrtf(red[0] + red[1] + red[2] + red[3]), 1e-12f);
                out[b * HH + tid] = z / nrm;
            }
            __syncthreads();
        }
    }
}

extern "C" void kernel_launch(void* const* d_in, const int* in_sizes, int n_in,
                              void* d_out, int out_size) {
    const int*   type_ids = (const int*)d_in[0];
    const int*   edges    = (const int*)d_in[1];
    const float* emb      = (const float*)d_in[2];
    const float* w1       = (const float*)d_in[3];
    const float* b1       = (const float*)d_in[4];
    const float* w2       = (const float*)d_in[5];
    const float* b2       = (const float*)d_in[6];
    float* out = (float*)d_out;

    gnn_all<<<GG, TT>>>(type_ids, edges, emb, w1, b1, w2, b2, out);
}

// round 4
// speedup vs baseline: 1.7544x; 1.1600x over previous
#include <cuda_runtime.h>

#define BB 8
#define NN 4096
#define EE 8190
#define VV 256
#define HH 128
#define TS 131072          // hash table slots (2^17, load factor 0.5)
#define TSM (TS - 1)
#define CAP 32             // adjacency capacity per node
#define GG 132             // persistent blocks (single wave on 148 SMs)
#define TT 256             // threads per block
#define SMEM_BYTES (VV * HH * 4)   // 128KB dynamic smem for emb1

// -------- scratch (device globals) --------
__device__ unsigned int g_tab[TS];           // dedup hash table (key+1, 0=empty)
__device__ int          g_rowcnt[BB * NN];   // unique out-degree per node
__device__ int          g_wcur[BB * NN];     // adjacency write cursor
__device__ float        g_insum[BB * NN];    // incoming dis sum per node
__device__ float        g_dis[BB * NN];      // deg^-1/2
__device__ float        g_emb1[VV * HH];     // emb @ w1^T
__device__ float        g_pooled[BB * HH];   // sum_j c_j * h_j
__device__ float2       g_adj[(size_t)BB * NN * CAP]; // (dis_j, type_j bits)
__device__ unsigned int g_bar_cnt;
__device__ unsigned int g_bar_gen;

__device__ __forceinline__ void gridbar() {
    __syncthreads();
    if (threadIdx.x == 0) {
        __threadfence();
        unsigned gen = *((volatile unsigned*)&g_bar_gen);
        if (atomicAdd(&g_bar_cnt, 1u) == gridDim.x - 1) {
            *((volatile unsigned*)&g_bar_cnt) = 0u;
            __threadfence();
            *((volatile unsigned*)&g_bar_gen) = gen + 1u;
        } else {
            while (*((volatile unsigned*)&g_bar_gen) == gen) { }
            __threadfence();
        }
    }
    __syncthreads();
}

extern __shared__ float s_emb1[];   // [VV*HH] staged emb1

__global__ void __launch_bounds__(TT, 1)
gnn_all(const int* __restrict__ type_ids, const int* __restrict__ edges,
        const float* __restrict__ emb, const float* __restrict__ w1,
        const float* __restrict__ b1, const float* __restrict__ w2,
        const float* __restrict__ b2, float* __restrict__ out) {
    const int tid  = threadIdx.x;
    const int gtid = blockIdx.x * TT + tid;
    const int gsz  = GG * TT;                 // 33792
    const int lane = tid & 31;
    const int gw   = gtid >> 5;
    const int nw   = gsz >> 5;                // 1056 warps

    // ---- P0: clear scratch ----
    for (int i = gtid; i < TS / 4; i += gsz)
        reinterpret_cast<uint4*>(g_tab)[i] = make_uint4(0u, 0u, 0u, 0u);
    for (int i = gtid; i < BB * NN; i += gsz) {
        g_rowcnt[i] = 0; g_wcur[i] = 0; g_insum[i] = 0.f;
    }
    for (int i = gtid; i < BB * HH; i += gsz) g_pooled[i] = 0.f;
    gridbar();

    // ---- P1: edge dedup (set semantics) + emb1 = emb @ w1^T (warp dots) ----
    for (int t = gtid; t < BB * EE; t += gsz) {
        int b = t / EE;
        int2 e = reinterpret_cast<const int2*>(edges)[t];
        unsigned key1 = (((unsigned)b << 24) | ((unsigned)e.x << 12) | (unsigned)e.y) + 1u;
        unsigned s = ((key1 * 0x9E3779B1u) >> 15) & TSM;
        while (true) {
            unsigned prev = atomicCAS(&g_tab[s], 0u, key1);
            if (prev == 0u) { atomicAdd(&g_rowcnt[b * NN + e.x], 1); break; }
            if (prev == key1) break;
            s = (s + 1) & TSM;
        }
    }
    for (int o = gw; o < VV * HH; o += nw) {
        int v = o >> 7, c = o & 127;
        const float* er = emb + v * HH;
        const float* wr = w1 + c * HH;
        float p = 0.f;
        #pragma unroll
        for (int q = 0; q < 4; q++) { int k = lane + q * 32; p = fmaf(er[k], wr[k], p); }
        #pragma unroll
        for (int off = 16; off; off >>= 1) p += __shfl_xor_sync(0xffffffffu, p, off);
        if (lane == 0) g_emb1[o] = p;
    }
    gridbar();

    // ---- P2+P3: dis array + hash sweep -> adjacency + insum (dis recomputed via MUFU) ----
    for (int i = gtid; i < BB * NN; i += gsz)
        g_dis[i] = rsqrtf(1.0f + (float)g_rowcnt[i]);
    for (int s = gtid; s < TS; s += gsz) {
        unsigned k1 = g_tab[s];
        if (!k1) continue;
        unsigned key = k1 - 1u;
        int b = key >> 24;
        int i = (key >> 12) & 4095;
        int j = key & 4095;
        int ni = b * NN + i;
        int nj = b * NN + j;
        float dj = rsqrtf(1.0f + (float)g_rowcnt[nj]);
        float di = rsqrtf(1.0f + (float)g_rowcnt[ni]);
        int c = atomicAdd(&g_wcur[ni], 1);
        if (c < CAP)
            g_adj[(size_t)ni * CAP + c] = make_float2(dj, __int_as_float(type_ids[nj]));
        atomicAdd(&g_insum[nj], di);
    }
    gridbar();

    // ---- P4: stage emb1 to smem; per node h = relu(di*(di*e1 + S) + b1); pool ----
    for (int i = tid; i < VV * HH; i += TT) s_emb1[i] = g_emb1[i];
    __syncthreads();
    {
        const int grp = (blockIdx.x << 1) | (tid >> 7);   // 264 groups of 128 threads
        const int t7  = tid & 127;
        const float bias = b1[t7];
        if (grp < 256) {                                   // one 128-node chunk per group
            int b = grp >> 5;
            int base = b * NN + (grp & 31) * 128;
            float acc = 0.f;

            float  di[2][4], ins[2][4];
            int    deg[2][4], ti[2][4];
            float4 q0[2][4], q1[2][4];

            // prime batch 0
            #pragma unroll
            for (int u = 0; u < 4; u++) {
                int ni = base + u;
                di[0][u]  = g_dis[ni];
                deg[0][u] = g_rowcnt[ni];
                ti[0][u]  = type_ids[ni];
                ins[0][u] = g_insum[ni];
                const float4* ap4 = reinterpret_cast<const float4*>(g_adj + (size_t)ni * CAP);
                q0[0][u] = ap4[0];
                q1[0][u] = ap4[1];
            }
            for (int n0 = 0; n0 < 128; n0 += 4) {
                int cur = (n0 >> 2) & 1, nxt = cur ^ 1;
                if (n0 + 4 < 128) {
                    #pragma unroll
                    for (int u = 0; u < 4; u++) {
                        int ni = base + n0 + 4 + u;
                        di[nxt][u]  = g_dis[ni];
                        deg[nxt][u] = g_rowcnt[ni];
                        ti[nxt][u]  = type_ids[ni];
                        ins[nxt][u] = g_insum[ni];
                        const float4* ap4 = reinterpret_cast<const float4*>(g_adj + (size_t)ni * CAP);
                        q0[nxt][u] = ap4[0];
                        q1[nxt][u] = ap4[1];
                    }
                }
                #pragma unroll
                for (int u = 0; u < 4; u++) {
                    int dg = deg[cur][u];
                    float dd = di[cur][u];
                    float s = dd * s_emb1[ti[cur][u] * HH + t7];
                    s = fmaf(dg > 0 ? q0[cur][u].x : 0.f,
                             s_emb1[(__float_as_int(q0[cur][u].y) & 255) * HH + t7], s);
                    s = fmaf(dg > 1 ? q0[cur][u].z : 0.f,
                             s_emb1[(__float_as_int(q0[cur][u].w) & 255) * HH + t7], s);
                    s = fmaf(dg > 2 ? q1[cur][u].x : 0.f,
                             s_emb1[(__float_as_int(q1[cur][u].y) & 255) * HH + t7], s);
                    s = fmaf(dg > 3 ? q1[cur][u].z : 0.f,
                             s_emb1[(__float_as_int(q1[cur][u].w) & 255) * HH + t7], s);
                    if (dg > 4) {                          // rare tail (P ~ 5%)
                        int dmax = min(dg, CAP);
                        const float2* ap = g_adj + (size_t)(base + n0 + u) * CAP;
                        for (int d = 4; d < dmax; d++) {
                            float2 en = ap[d];
                            s = fmaf(en.x, s_emb1[(__float_as_int(en.y) & 255) * HH + t7], s);
                        }
                    }
                    float hv = fmaxf(fmaf(dd, s, bias), 0.f);
                    acc = fmaf(dd * (dd + ins[cur][u]), hv, acc);
                }
            }
            atomicAdd(&g_pooled[b * HH + t7], acc);
        }
    }
    gridbar();

    // ---- P5+P6: blocks 0..7: z = (pooled/N)@w2^T + b2 ; L2-normalize ; write ----
    if (blockIdx.x < BB) {
        const int b = blockIdx.x;
        __shared__ float xs[HH];
        __shared__ float zsh[HH];
        __shared__ float nsum;
        if (tid < HH) xs[tid] = g_pooled[b * HH + tid] * (1.0f / NN);
        if (tid == 0) nsum = 0.f;
        __syncthreads();
        const int w = tid >> 5;                 // 8 warps -> 16 rows each
        float sqp = 0.f;
        for (int r = w * 16; r < w * 16 + 16; r++) {
            const float* wr = w2 + r * HH;
            float p = 0.f;
            #pragma unroll
            for (int q = 0; q < 4; q++) { int k = lane + q * 32; p = fmaf(wr[k], xs[k], p); }
            #pragma unroll
            for (int off = 16; off; off >>= 1) p += __shfl_xor_sync(0xffffffffu, p, off);
            if (lane == 0) {
                float z = p + b2[r];
                zsh[r] = z;
                sqp = fmaf(z, z, sqp);
            }
        }
        if (lane == 0) atomicAdd(&nsum, sqp);
        __syncthreads();
        if (tid < HH) {
            float nrm = fmaxf(sqrtf(nsum), 1e-12f);
            out[b * HH + tid] = zsh[tid] / nrm;
        }
    }
}

extern "C" void kernel_launch(void* const* d_in, const int* in_sizes, int n_in,
                              void* d_out, int out_size) {
    const int*   type_ids = (const int*)d_in[0];
    const int*   edges    = (const int*)d_in[1];
    const float* emb      = (const float*)d_in[2];
    const float* w1       = (const float*)d_in[3];
    const float* b1       = (const float*)d_in[4];
    const float* w2       = (const float*)d_in[5];
    const float* b2       = (const float*)d_in[6];
    float* out = (float*)d_out;

    static int smem_set = 0;
    if (!smem_set) {
        cudaFuncSetAttribute(gnn_all, cudaFuncAttributeMaxDynamicSharedMemorySize, SMEM_BYTES);
        smem_set = 1;
    }
    gnn_all<<<GG, TT, SMEM_BYTES>>>(type_ids, edges, emb, w1, b1, w2, b2, out);
}

// round 5
// speedup vs baseline: 2.9807x; 1.6989x over previous
#include <cuda_runtime.h>

#define BB 8
#define NN 4096
#define EE 8190
#define VV 256
#define HH 128
#define TS 131072          // hash table slots (2^17, load factor 0.5)
#define TSM (TS - 1)
#define CAP 32             // adjacency capacity per node
#define GG 132             // persistent blocks (single wave on 148 SMs)
#define TT 1024            // threads per block (32 warps/SM for latency hiding)
#define SMEM_BYTES (VV * HH * 4)   // 128KB dynamic smem for emb1

// -------- scratch (device globals) --------
__device__ unsigned int g_tab[TS];           // dedup hash table (key+1, 0=empty)
__device__ int          g_rowcnt[BB * NN];   // unique out-degree per node
__device__ int          g_wcur[BB * NN];     // adjacency write cursor
__device__ float        g_insum[BB * NN];    // incoming dis sum per node
__device__ float        g_dis[BB * NN];      // deg^-1/2
__device__ float        g_emb1[VV * HH];     // emb @ w1^T
__device__ float        g_pooled[BB * HH];   // sum_j c_j * h_j
__device__ float2       g_adj[(size_t)BB * NN * CAP]; // (dis_j, type_j bits)
__device__ unsigned int g_bar_cnt;
__device__ unsigned int g_bar_gen;

__device__ __forceinline__ void gridbar() {
    __syncthreads();
    if (threadIdx.x == 0) {
        __threadfence();
        unsigned gen = *((volatile unsigned*)&g_bar_gen);
        if (atomicAdd(&g_bar_cnt, 1u) == gridDim.x - 1) {
            *((volatile unsigned*)&g_bar_cnt) = 0u;
            __threadfence();
            *((volatile unsigned*)&g_bar_gen) = gen + 1u;
        } else {
            while (*((volatile unsigned*)&g_bar_gen) == gen) { }
            __threadfence();
        }
    }
    __syncthreads();
}

extern __shared__ float s_emb1[];   // [VV*HH] staged emb1

__global__ void __launch_bounds__(TT, 1)
gnn_all(const int* __restrict__ type_ids, const int* __restrict__ edges,
        const float* __restrict__ emb, const float* __restrict__ w1,
        const float* __restrict__ b1, const float* __restrict__ w2,
        const float* __restrict__ b2, float* __restrict__ out) {
    const int tid  = threadIdx.x;
    const int gtid = blockIdx.x * TT + tid;
    const int gsz  = GG * TT;                 // 135168
    const int lane = tid & 31;
    const int gw   = gtid >> 5;
    const int nw   = gsz >> 5;                // 4224 warps

    // ---- P0: clear scratch ----
    for (int i = gtid; i < TS / 4; i += gsz)
        reinterpret_cast<uint4*>(g_tab)[i] = make_uint4(0u, 0u, 0u, 0u);
    for (int i = gtid; i < BB * NN; i += gsz) {
        g_rowcnt[i] = 0; g_wcur[i] = 0; g_insum[i] = 0.f;
    }
    for (int i = gtid; i < BB * HH; i += gsz) g_pooled[i] = 0.f;
    gridbar();

    // ---- P1: edge dedup (set semantics) + emb1 = emb @ w1^T (warp dots) ----
    for (int t = gtid; t < BB * EE; t += gsz) {
        int b = t / EE;
        int2 e = reinterpret_cast<const int2*>(edges)[t];
        unsigned key1 = (((unsigned)b << 24) | ((unsigned)e.x << 12) | (unsigned)e.y) + 1u;
        unsigned s = ((key1 * 0x9E3779B1u) >> 15) & TSM;
        while (true) {
            unsigned prev = atomicCAS(&g_tab[s], 0u, key1);
            if (prev == 0u) { atomicAdd(&g_rowcnt[b * NN + e.x], 1); break; }
            if (prev == key1) break;
            s = (s + 1) & TSM;
        }
    }
    for (int o = gw; o < VV * HH; o += nw) {
        int v = o >> 7, c = o & 127;
        const float* er = emb + v * HH;
        const float* wr = w1 + c * HH;
        float p = 0.f;
        #pragma unroll
        for (int q = 0; q < 4; q++) { int k = lane + q * 32; p = fmaf(er[k], wr[k], p); }
        #pragma unroll
        for (int off = 16; off; off >>= 1) p += __shfl_xor_sync(0xffffffffu, p, off);
        if (lane == 0) g_emb1[o] = p;
    }
    gridbar();

    // ---- P2+P3: dis array + hash sweep -> adjacency + insum ----
    for (int i = gtid; i < BB * NN; i += gsz)
        g_dis[i] = rsqrtf(1.0f + (float)g_rowcnt[i]);
    for (int s = gtid; s < TS; s += gsz) {
        unsigned k1 = g_tab[s];
        if (!k1) continue;
        unsigned key = k1 - 1u;
        int b = key >> 24;
        int i = (key >> 12) & 4095;
        int j = key & 4095;
        int ni = b * NN + i;
        int nj = b * NN + j;
        float dj = rsqrtf(1.0f + (float)g_rowcnt[nj]);
        float di = rsqrtf(1.0f + (float)g_rowcnt[ni]);
        int c = atomicAdd(&g_wcur[ni], 1);
        if (c < CAP)
            g_adj[(size_t)ni * CAP + c] = make_float2(dj, __int_as_float(type_ids[nj]));
        atomicAdd(&g_insum[nj], di);
    }
    gridbar();

    // ---- P4: stage emb1 to smem; per node h = relu(di*(di*e1 + S) + b1); pool ----
    for (int i = tid; i < VV * HH / 4; i += TT)
        reinterpret_cast<float4*>(s_emb1)[i] = reinterpret_cast<const float4*>(g_emb1)[i];
    __syncthreads();
    {
        const int grp = blockIdx.x * (TT / 128) + (tid >> 7);  // 1056 groups of 128 thr
        const int t7  = tid & 127;
        const float bias = b1[t7];
        if (grp < 1024) {                                      // one 32-node chunk per group
            int b = grp >> 7;
            int base = b * NN + (grp & 127) * 32;
            float acc = 0.f;

            // 1-node double buffer: meta + first 2 adjacency entries
            float di[2], ins[2]; int deg[2], ti[2]; float4 q0[2];
            {
                int ni = base;
                di[0]  = g_dis[ni];
                deg[0] = g_rowcnt[ni];
                ti[0]  = type_ids[ni];
                ins[0] = g_insum[ni];
                q0[0]  = reinterpret_cast<const float4*>(g_adj + (size_t)ni * CAP)[0];
            }
            for (int n = 0; n < 32; n++) {
                int cur = n & 1, nxt = cur ^ 1;
                if (n + 1 < 32) {
                    int ni = base + n + 1;
                    di[nxt]  = g_dis[ni];
                    deg[nxt] = g_rowcnt[ni];
                    ti[nxt]  = type_ids[ni];
                    ins[nxt] = g_insum[ni];
                    q0[nxt]  = reinterpret_cast<const float4*>(g_adj + (size_t)ni * CAP)[0];
                }
                int dg = deg[cur];
                float dd = di[cur];
                float s = dd * s_emb1[ti[cur] * HH + t7];
                s = fmaf(dg > 0 ? q0[cur].x : 0.f,
                         s_emb1[(__float_as_int(q0[cur].y) & 255) * HH + t7], s);
                s = fmaf(dg > 1 ? q0[cur].z : 0.f,
                         s_emb1[(__float_as_int(q0[cur].w) & 255) * HH + t7], s);
                if (dg > 2) {                          // tail (P ~ 32%/edge dist; cheap)
                    int dmax = min(dg, CAP);
                    const float2* ap = g_adj + (size_t)(base + n) * CAP;
                    for (int d = 2; d < dmax; d++) {
                        float2 en = ap[d];
                        s = fmaf(en.x, s_emb1[(__float_as_int(en.y) & 255) * HH + t7], s);
                    }
                }
                float hv = fmaxf(fmaf(dd, s, bias), 0.f);
                acc = fmaf(dd * (dd + ins[cur]), hv, acc);
            }
            atomicAdd(&g_pooled[b * HH + t7], acc);
        }
    }
    gridbar();

    // ---- P5+P6: blocks 0..7: z = (pooled/N)@w2^T + b2 ; L2-normalize ; write ----
    if (blockIdx.x < BB && tid < 256) {
        const int b = blockIdx.x;
        __shared__ float xs[HH];
        __shared__ float zsh[HH];
        __shared__ float nsum;
        if (tid < HH) xs[tid] = g_pooled[b * HH + tid] * (1.0f / NN);
        if (tid == 0) nsum = 0.f;
        __syncwarp();
        asm volatile("bar.sync 1, 256;" ::: "memory");
        const int w = tid >> 5;                 // 8 warps -> 16 rows each
        float sqp = 0.f;
        for (int r = w * 16; r < w * 16 + 16; r++) {
            const float* wr = w2 + r * HH;
            float p = 0.f;
            #pragma unroll
            for (int q = 0; q < 4; q++) { int k = lane + q * 32; p = fmaf(wr[k], xs[k], p); }
            #pragma unroll
            for (int off = 16; off; off >>= 1) p += __shfl_xor_sync(0xffffffffu, p, off);
            if (lane == 0) {
                float z = p + b2[r];
                zsh[r] = z;
                sqp = fmaf(z, z, sqp);
            }
        }
        if (lane == 0) atomicAdd(&nsum, sqp);
        asm volatile("bar.sync 1, 256;" ::: "memory");
        if (tid < HH) {
            float nrm = fmaxf(sqrtf(nsum), 1e-12f);
            out[b * HH + tid] = zsh[tid] / nrm;
        }
    }
}

extern "C" void kernel_launch(void* const* d_in, const int* in_sizes, int n_in,
                              void* d_out, int out_size) {
    const int*   type_ids = (const int*)d_in[0];
    const int*   edges    = (const int*)d_in[1];
    const float* emb      = (const float*)d_in[2];
    const float* w1       = (const float*)d_in[3];
    const float* b1       = (const float*)d_in[4];
    const float* w2       = (const float*)d_in[5];
    const float* b2       = (const float*)d_in[6];
    float* out = (float*)d_out;

    static int smem_set = 0;
    if (!smem_set) {
        cudaFuncSetAttribute(gnn_all, cudaFuncAttributeMaxDynamicSharedMemorySize, SMEM_BYTES);
        smem_set = 1;
    }
    gnn_all<<<GG, TT, SMEM_BYTES>>>(type_ids, edges, emb, w1, b1, w2, b2, out);
}